// round 12
// baseline (speedup 1.0000x reference)
#include <cuda_runtime.h>

#define NCLS 20
#define NHALF 10
#define NSUP 100
#define NQRY 300
#define DDIM 640
#define NTASK 256
#define THREADS 256
#define ROW16 (DDIM / 4)      // 160 16-byte elements per row
#define NCHUNK (DDIM / 32)    // 20 chunks: 8 lanes x 4 floats
#define NGRP 19               // ceil(300/16): 16 queries per warp-group (4 per subgroup)

__device__ float g_task_loss[NTASK];
__device__ unsigned int g_ticket = 0;

__device__ __forceinline__ unsigned long long ffma2(unsigned long long a,
                                                    unsigned long long b,
                                                    unsigned long long c) {
    unsigned long long d;
    asm("fma.rn.f32x2 %0, %1, %2, %3;" : "=l"(d) : "l"(a), "l"(b), "l"(c));
    return d;
}
__device__ __forceinline__ unsigned long long fadd2(unsigned long long a,
                                                    unsigned long long b) {
    unsigned long long d;
    asm("add.rn.f32x2 %0, %1, %2;" : "=l"(d) : "l"(a), "l"(b));
    return d;
}
__device__ __forceinline__ float2 unpk2(unsigned long long v) {
    float lo, hi;
    asm("mov.b64 {%0, %1}, %2;" : "=f"(lo), "=f"(hi) : "l"(v));
    return make_float2(lo, hi);
}

extern __shared__ float smem_raw[];

__global__ __launch_bounds__(THREADS, 2)
void proto_loss_kernel(const float* __restrict__ sup,
                       const float* __restrict__ qry,
                       const int* __restrict__ tsup,
                       const int* __restrict__ tqry,
                       float* __restrict__ out) {
    float* proto  = smem_raw;                    // [20][640]
    float* psq    = proto + NCLS * DDIM;         // [20]
    float* wsum   = psq + NCLS;                  // [8]
    int*   counts = (int*)(wsum + 8);            // [20]
    int*   labels = counts + NCLS;               // [100]
    int*   tqs    = labels + NSUP;               // [300]
    int*   flag   = tqs + NQRY;                  // [1]

    const int b    = blockIdx.x;
    const int tid  = threadIdx.x;
    const int lane = tid & 31;
    const int wid  = tid >> 5;
    const int sub  = (lane >> 3);   // subgroup 0..3
    const int sl   = lane & 7;      // lane within subgroup

    // ======== Phase 1: prototypes (float4 path) ========
    for (int i = tid; i < NCLS * DDIM; i += THREADS) proto[i] = 0.f;
    if (tid < NCLS) counts[tid] = 0;
    if (tid < NSUP) labels[tid] = tsup[b * NSUP + tid];
    for (int i = tid; i < NQRY; i += THREADS) tqs[i] = tqry[b * NQRY + i];
    __syncthreads();
    if (tid < NSUP) atomicAdd(&counts[labels[tid]], 1);

    if (tid < ROW16) {   // 160 threads: one float4 column each
        const float4* sup4 = (const float4*)(sup + (size_t)b * NSUP * DDIM);
        float4* proto4 = (float4*)proto;
        int cur = labels[0];
        float4 run = make_float4(0.f, 0.f, 0.f, 0.f);
        #pragma unroll 5
        for (int s = 0; s < NSUP; s++) {
            int L = labels[s];
            if (L != cur) {
                float4 p = proto4[cur * ROW16 + tid];
                p.x += run.x; p.y += run.y; p.z += run.z; p.w += run.w;
                proto4[cur * ROW16 + tid] = p;
                run = make_float4(0.f, 0.f, 0.f, 0.f);
                cur = L;
            }
            float4 v = sup4[s * ROW16 + tid];
            run.x += v.x; run.y += v.y; run.z += v.z; run.w += v.w;
        }
        float4 p = proto4[cur * ROW16 + tid];
        p.x += run.x; p.y += run.y; p.z += run.z; p.w += run.w;
        proto4[cur * ROW16 + tid] = p;
    }
    __syncthreads();

    #pragma unroll
    for (int c = 0; c < NCLS; c++) {
        float inv = 1.f / (float)counts[c];
        for (int d = tid; d < DDIM; d += THREADS) proto[c * DDIM + d] *= inv;
    }
    __syncthreads();

    for (int c = wid; c < NCLS; c += 8) {
        float v = 0.f;
        for (int d = lane; d < DDIM; d += 32) {
            float p = proto[c * DDIM + d];
            v = fmaf(p, p, v);
        }
        #pragma unroll
        for (int o = 16; o; o >>= 1) v += __shfl_xor_sync(0xffffffffu, v, o);
        if (!lane) psq[c] = v;
    }
    __syncthreads();

    // ======== Phase 2: 4 queries/subgroup, classes 10+10, online LSE ========
    const ulonglong2* q2 = (const ulonglong2*)(qry + (size_t)b * NQRY * DDIM);
    const ulonglong2* prow = (const ulonglong2*)proto + sl;
    float nll = 0.f;

    for (int g = wid; g < NGRP; g += 8) {
        const int qbase = g * 16 + sub * 4;   // queries qbase..qbase+3
        const ulonglong2* qr[4];
        int tgt[4];
        #pragma unroll
        for (int qi = 0; qi < 4; qi++) {
            int q = qbase + qi;
            int qc = q < NQRY ? q : NQRY - 1;
            qr[qi] = q2 + (size_t)qc * ROW16 + sl;
            tgt[qi] = tqs[qc];
        }

        // online LSE state per query
        float m0 = -1e30f, m1 = -1e30f, m2 = -1e30f, m3 = -1e30f;
        float s0 = 0.f, s1 = 0.f, s2 = 0.f, s3 = 0.f;
        float st0 = 0.f, st1 = 0.f, st2 = 0.f, st3 = 0.f;

        #pragma unroll
        for (int half = 0; half < 2; half++) {
            const int cb = half * NHALF;
            unsigned long long a0[NHALF], a1[NHALF], a2[NHALF], a3[NHALF];
            #pragma unroll
            for (int c = 0; c < NHALF; c++) {
                a0[c] = 0ull; a1[c] = 0ull; a2[c] = 0ull; a3[c] = 0ull;
            }

            #pragma unroll 5
            for (int ch = 0; ch < NCHUNK; ch++) {
                ulonglong2 v0 = qr[0][ch * 8];
                ulonglong2 v1 = qr[1][ch * 8];
                ulonglong2 v2 = qr[2][ch * 8];
                ulonglong2 v3 = qr[3][ch * 8];
                #pragma unroll
                for (int c = 0; c < NHALF; c++) {
                    ulonglong2 pv = prow[(cb + c) * ROW16 + ch * 8];
                    a0[c] = ffma2(v0.x, pv.x, a0[c]);
                    a0[c] = ffma2(v0.y, pv.y, a0[c]);
                    a1[c] = ffma2(v1.x, pv.x, a1[c]);
                    a1[c] = ffma2(v1.y, pv.y, a1[c]);
                    a2[c] = ffma2(v2.x, pv.x, a2[c]);
                    a2[c] = ffma2(v2.y, pv.y, a2[c]);
                    a3[c] = ffma2(v3.x, pv.x, a3[c]);
                    a3[c] = ffma2(v3.y, pv.y, a3[c]);
                }
            }

            // 3-round butterfly within the 8-lane subgroup
            #pragma unroll
            for (int c = 0; c < NHALF; c++) {
                #pragma unroll
                for (int o = 4; o; o >>= 1) {
                    a0[c] = fadd2(a0[c], __shfl_xor_sync(0xffffffffu, a0[c], o));
                    a1[c] = fadd2(a1[c], __shfl_xor_sync(0xffffffffu, a1[c], o));
                    a2[c] = fadd2(a2[c], __shfl_xor_sync(0xffffffffu, a2[c], o));
                    a3[c] = fadd2(a3[c], __shfl_xor_sync(0xffffffffu, a3[c], o));
                }
            }

            // half-epilogue: recompute sv from live accs; max pass then exp pass
            float hm0 = -1e30f, hm1 = -1e30f, hm2 = -1e30f, hm3 = -1e30f;
            #pragma unroll
            for (int c = 0; c < NHALF; c++) {
                const float nps = -psq[cb + c];
                float2 x;
                x = unpk2(a0[c]); float v0s = fmaf(2.f, x.x + x.y, nps);
                x = unpk2(a1[c]); float v1s = fmaf(2.f, x.x + x.y, nps);
                x = unpk2(a2[c]); float v2s = fmaf(2.f, x.x + x.y, nps);
                x = unpk2(a3[c]); float v3s = fmaf(2.f, x.x + x.y, nps);
                hm0 = fmaxf(hm0, v0s); hm1 = fmaxf(hm1, v1s);
                hm2 = fmaxf(hm2, v2s); hm3 = fmaxf(hm3, v3s);
                if (cb + c == tgt[0]) st0 = v0s;
                if (cb + c == tgt[1]) st1 = v1s;
                if (cb + c == tgt[2]) st2 = v2s;
                if (cb + c == tgt[3]) st3 = v3s;
            }
            float hs0 = 0.f, hs1 = 0.f, hs2 = 0.f, hs3 = 0.f;
            #pragma unroll
            for (int c = 0; c < NHALF; c++) {
                const float nps = -psq[cb + c];
                float2 x;
                x = unpk2(a0[c]); hs0 += __expf(fmaf(2.f, x.x + x.y, nps) - hm0);
                x = unpk2(a1[c]); hs1 += __expf(fmaf(2.f, x.x + x.y, nps) - hm1);
                x = unpk2(a2[c]); hs2 += __expf(fmaf(2.f, x.x + x.y, nps) - hm2);
                x = unpk2(a3[c]); hs3 += __expf(fmaf(2.f, x.x + x.y, nps) - hm3);
            }
            // merge half into online state
            float nm;
            nm = fmaxf(m0, hm0); s0 = s0 * __expf(m0 - nm) + hs0 * __expf(hm0 - nm); m0 = nm;
            nm = fmaxf(m1, hm1); s1 = s1 * __expf(m1 - nm) + hs1 * __expf(hm1 - nm); m1 = nm;
            nm = fmaxf(m2, hm2); s2 = s2 * __expf(m2 - nm) + hs2 * __expf(hm2 - nm); m2 = nm;
            nm = fmaxf(m3, hm3); s3 = s3 * __expf(m3 - nm) + hs3 * __expf(hm3 - nm); m3 = nm;
        }

        // accumulate NLL for valid queries
        if (qbase + 0 < NQRY) nll += (m0 + __logf(s0)) - st0;
        if (qbase + 1 < NQRY) nll += (m1 + __logf(s1)) - st1;
        if (qbase + 2 < NQRY) nll += (m2 + __logf(s2)) - st2;
        if (qbase + 3 < NQRY) nll += (m3 + __logf(s3)) - st3;
    }

    // all 8 lanes of a subgroup hold identical nll; full-warp sum / 8 is exact
    #pragma unroll
    for (int o = 16; o; o >>= 1) nll += __shfl_xor_sync(0xffffffffu, nll, o);
    nll *= 0.125f;

    if (!lane) wsum[wid] = nll;
    __syncthreads();
    if (tid == 0) {
        float t = 0.f;
        #pragma unroll
        for (int w = 0; w < 8; w++) t += wsum[w];
        g_task_loss[b] = t * (1.f / (float)NQRY);
        __threadfence();
        unsigned int v = atomicAdd(&g_ticket, 1u);
        *flag = ((v + 1u) % NTASK == 0u) ? 1 : 0;
    }
    __syncthreads();

    // last-arriving CTA performs the deterministic final reduction
    if (*flag) {
        __threadfence();
        float x = __ldcg(&g_task_loss[tid]);
        float* red = proto;   // reuse smem
        red[tid] = x;
        __syncthreads();
        #pragma unroll
        for (int off = 128; off; off >>= 1) {
            if (tid < off) red[tid] += red[tid + off];
            __syncthreads();
        }
        if (tid == 0) out[0] = red[0] * (1.f / (float)NTASK);
    }
}

extern "C" void kernel_launch(void* const* d_in, const int* in_sizes, int n_in,
                              void* d_out, int out_size) {
    const float* sup = (const float*)d_in[0];
    const float* qry = (const float*)d_in[1];
    const int*   ts  = (const int*)d_in[2];
    const int*   tq  = (const int*)d_in[3];
    float* out = (float*)d_out;

    const size_t SMEM = (size_t)(NCLS * DDIM + NCLS + 8) * sizeof(float)
                      + (size_t)(NCLS + NSUP + NQRY + 1) * sizeof(int);
    cudaFuncSetAttribute(proto_loss_kernel,
                         cudaFuncAttributeMaxDynamicSharedMemorySize, (int)SMEM);
    proto_loss_kernel<<<NTASK, THREADS, SMEM>>>(sup, qry, ts, tq, out);
}

// round 13
// speedup vs baseline: 1.1069x; 1.1069x over previous
#include <cuda_runtime.h>

#define NCLS 20
#define NPASS 4
#define NPC 5                 // classes per pass
#define NSUP 100
#define NQRY 300
#define DDIM 640
#define NTASK 256
#define THREADS 256
#define ROW16 (DDIM / 4)      // 160 16-byte elements per row
#define NCHUNK (DDIM / 32)    // 20 chunks: 8 lanes x 4 floats
#define NGRP 19               // ceil(300/16): 16 queries per warp-group (4 per subgroup)

__device__ float g_task_loss[NTASK];
__device__ unsigned int g_ticket = 0;

__device__ __forceinline__ unsigned long long ffma2(unsigned long long a,
                                                    unsigned long long b,
                                                    unsigned long long c) {
    unsigned long long d;
    asm("fma.rn.f32x2 %0, %1, %2, %3;" : "=l"(d) : "l"(a), "l"(b), "l"(c));
    return d;
}
__device__ __forceinline__ unsigned long long fadd2(unsigned long long a,
                                                    unsigned long long b) {
    unsigned long long d;
    asm("add.rn.f32x2 %0, %1, %2;" : "=l"(d) : "l"(a), "l"(b));
    return d;
}
__device__ __forceinline__ float2 unpk2(unsigned long long v) {
    float lo, hi;
    asm("mov.b64 {%0, %1}, %2;" : "=f"(lo), "=f"(hi) : "l"(v));
    return make_float2(lo, hi);
}

extern __shared__ float smem_raw[];

__global__ __launch_bounds__(THREADS, 2)
void proto_loss_kernel(const float* __restrict__ sup,
                       const float* __restrict__ qry,
                       const int* __restrict__ tsup,
                       const int* __restrict__ tqry,
                       float* __restrict__ out) {
    float* proto  = smem_raw;                    // [20][640]
    float* psq    = proto + NCLS * DDIM;         // [20]
    float* wsum   = psq + NCLS;                  // [8]
    int*   counts = (int*)(wsum + 8);            // [20]
    int*   labels = counts + NCLS;               // [100]
    int*   tqs    = labels + NSUP;               // [300]
    int*   flag   = tqs + NQRY;                  // [1]

    const int b    = blockIdx.x;
    const int tid  = threadIdx.x;
    const int lane = tid & 31;
    const int wid  = tid >> 5;
    const int sub  = (lane >> 3);   // subgroup 0..3
    const int sl   = lane & 7;      // lane within subgroup

    // ======== Phase 1: prototypes (float4 path) ========
    for (int i = tid; i < NCLS * DDIM; i += THREADS) proto[i] = 0.f;
    if (tid < NCLS) counts[tid] = 0;
    if (tid < NSUP) labels[tid] = tsup[b * NSUP + tid];
    for (int i = tid; i < NQRY; i += THREADS) tqs[i] = tqry[b * NQRY + i];
    __syncthreads();
    if (tid < NSUP) atomicAdd(&counts[labels[tid]], 1);

    if (tid < ROW16) {   // 160 threads: one float4 column each
        const float4* sup4 = (const float4*)(sup + (size_t)b * NSUP * DDIM);
        float4* proto4 = (float4*)proto;
        int cur = labels[0];
        float4 run = make_float4(0.f, 0.f, 0.f, 0.f);
        #pragma unroll 5
        for (int s = 0; s < NSUP; s++) {
            int L = labels[s];
            if (L != cur) {
                float4 p = proto4[cur * ROW16 + tid];
                p.x += run.x; p.y += run.y; p.z += run.z; p.w += run.w;
                proto4[cur * ROW16 + tid] = p;
                run = make_float4(0.f, 0.f, 0.f, 0.f);
                cur = L;
            }
            float4 v = sup4[s * ROW16 + tid];
            run.x += v.x; run.y += v.y; run.z += v.z; run.w += v.w;
        }
        float4 p = proto4[cur * ROW16 + tid];
        p.x += run.x; p.y += run.y; p.z += run.z; p.w += run.w;
        proto4[cur * ROW16 + tid] = p;
    }
    __syncthreads();

    #pragma unroll
    for (int c = 0; c < NCLS; c++) {
        float inv = 1.f / (float)counts[c];
        for (int d = tid; d < DDIM; d += THREADS) proto[c * DDIM + d] *= inv;
    }
    __syncthreads();

    for (int c = wid; c < NCLS; c += 8) {
        float v = 0.f;
        for (int d = lane; d < DDIM; d += 32) {
            float p = proto[c * DDIM + d];
            v = fmaf(p, p, v);
        }
        #pragma unroll
        for (int o = 16; o; o >>= 1) v += __shfl_xor_sync(0xffffffffu, v, o);
        if (!lane) psq[c] = v;
    }
    __syncthreads();

    // ======== Phase 2: 4 queries/subgroup, 4 passes of 5 classes, online LSE ========
    const ulonglong2* q2 = (const ulonglong2*)(qry + (size_t)b * NQRY * DDIM);
    const ulonglong2* prow = (const ulonglong2*)proto + sl;
    float nll = 0.f;

    for (int g = wid; g < NGRP; g += 8) {
        const int qbase = g * 16 + sub * 4;   // queries qbase..qbase+3
        const int qc0 = (qbase + 0) < NQRY ? (qbase + 0) : NQRY - 1;
        const int qc1 = (qbase + 1) < NQRY ? (qbase + 1) : NQRY - 1;
        const int qc2 = (qbase + 2) < NQRY ? (qbase + 2) : NQRY - 1;
        const int qc3 = (qbase + 3) < NQRY ? (qbase + 3) : NQRY - 1;
        const ulonglong2* qr0 = q2 + (size_t)qc0 * ROW16 + sl;
        const ulonglong2* qr1 = q2 + (size_t)qc1 * ROW16 + sl;
        const ulonglong2* qr2 = q2 + (size_t)qc2 * ROW16 + sl;
        const ulonglong2* qr3 = q2 + (size_t)qc3 * ROW16 + sl;
        const int t0 = tqs[qc0], t1 = tqs[qc1], t2 = tqs[qc2], t3 = tqs[qc3];

        // online LSE state per query
        float m0 = -1e30f, m1 = -1e30f, m2 = -1e30f, m3 = -1e30f;
        float s0 = 0.f, s1 = 0.f, s2 = 0.f, s3 = 0.f;
        float st0 = 0.f, st1 = 0.f, st2 = 0.f, st3 = 0.f;

        #pragma unroll
        for (int pass = 0; pass < NPASS; pass++) {
            const int cb = pass * NPC;
            unsigned long long a0[NPC], a1[NPC], a2[NPC], a3[NPC];
            #pragma unroll
            for (int c = 0; c < NPC; c++) {
                a0[c] = 0ull; a1[c] = 0ull; a2[c] = 0ull; a3[c] = 0ull;
            }

            #pragma unroll 5
            for (int ch = 0; ch < NCHUNK; ch++) {
                ulonglong2 v0 = qr0[ch * 8];
                ulonglong2 v1 = qr1[ch * 8];
                ulonglong2 v2 = qr2[ch * 8];
                ulonglong2 v3 = qr3[ch * 8];
                #pragma unroll
                for (int c = 0; c < NPC; c++) {
                    ulonglong2 pv = prow[(cb + c) * ROW16 + ch * 8];
                    a0[c] = ffma2(v0.x, pv.x, a0[c]);
                    a0[c] = ffma2(v0.y, pv.y, a0[c]);
                    a1[c] = ffma2(v1.x, pv.x, a1[c]);
                    a1[c] = ffma2(v1.y, pv.y, a1[c]);
                    a2[c] = ffma2(v2.x, pv.x, a2[c]);
                    a2[c] = ffma2(v2.y, pv.y, a2[c]);
                    a3[c] = ffma2(v3.x, pv.x, a3[c]);
                    a3[c] = ffma2(v3.y, pv.y, a3[c]);
                }
            }

            // 3-round butterfly within the 8-lane subgroup
            #pragma unroll
            for (int c = 0; c < NPC; c++) {
                #pragma unroll
                for (int o = 4; o; o >>= 1) {
                    a0[c] = fadd2(a0[c], __shfl_xor_sync(0xffffffffu, a0[c], o));
                    a1[c] = fadd2(a1[c], __shfl_xor_sync(0xffffffffu, a1[c], o));
                    a2[c] = fadd2(a2[c], __shfl_xor_sync(0xffffffffu, a2[c], o));
                    a3[c] = fadd2(a3[c], __shfl_xor_sync(0xffffffffu, a3[c], o));
                }
            }

            // pass-epilogue: max pass then exp pass from live accs
            float hm0 = -1e30f, hm1 = -1e30f, hm2 = -1e30f, hm3 = -1e30f;
            #pragma unroll
            for (int c = 0; c < NPC; c++) {
                const float nps = -psq[cb + c];
                float2 x;
                x = unpk2(a0[c]); float v0s = fmaf(2.f, x.x + x.y, nps);
                x = unpk2(a1[c]); float v1s = fmaf(2.f, x.x + x.y, nps);
                x = unpk2(a2[c]); float v2s = fmaf(2.f, x.x + x.y, nps);
                x = unpk2(a3[c]); float v3s = fmaf(2.f, x.x + x.y, nps);
                hm0 = fmaxf(hm0, v0s); hm1 = fmaxf(hm1, v1s);
                hm2 = fmaxf(hm2, v2s); hm3 = fmaxf(hm3, v3s);
                if (cb + c == t0) st0 = v0s;
                if (cb + c == t1) st1 = v1s;
                if (cb + c == t2) st2 = v2s;
                if (cb + c == t3) st3 = v3s;
            }
            float hs0 = 0.f, hs1 = 0.f, hs2 = 0.f, hs3 = 0.f;
            #pragma unroll
            for (int c = 0; c < NPC; c++) {
                const float nps = -psq[cb + c];
                float2 x;
                x = unpk2(a0[c]); hs0 += __expf(fmaf(2.f, x.x + x.y, nps) - hm0);
                x = unpk2(a1[c]); hs1 += __expf(fmaf(2.f, x.x + x.y, nps) - hm1);
                x = unpk2(a2[c]); hs2 += __expf(fmaf(2.f, x.x + x.y, nps) - hm2);
                x = unpk2(a3[c]); hs3 += __expf(fmaf(2.f, x.x + x.y, nps) - hm3);
            }
            // merge pass into online state
            float nm;
            nm = fmaxf(m0, hm0); s0 = s0 * __expf(m0 - nm) + hs0 * __expf(hm0 - nm); m0 = nm;
            nm = fmaxf(m1, hm1); s1 = s1 * __expf(m1 - nm) + hs1 * __expf(hm1 - nm); m1 = nm;
            nm = fmaxf(m2, hm2); s2 = s2 * __expf(m2 - nm) + hs2 * __expf(hm2 - nm); m2 = nm;
            nm = fmaxf(m3, hm3); s3 = s3 * __expf(m3 - nm) + hs3 * __expf(hm3 - nm); m3 = nm;
        }

        // accumulate NLL for valid queries
        if (qbase + 0 < NQRY) nll += (m0 + __logf(s0)) - st0;
        if (qbase + 1 < NQRY) nll += (m1 + __logf(s1)) - st1;
        if (qbase + 2 < NQRY) nll += (m2 + __logf(s2)) - st2;
        if (qbase + 3 < NQRY) nll += (m3 + __logf(s3)) - st3;
    }

    // all 8 lanes of a subgroup hold identical nll; full-warp sum / 8 is exact
    #pragma unroll
    for (int o = 16; o; o >>= 1) nll += __shfl_xor_sync(0xffffffffu, nll, o);
    nll *= 0.125f;

    if (!lane) wsum[wid] = nll;
    __syncthreads();
    if (tid == 0) {
        float t = 0.f;
        #pragma unroll
        for (int w = 0; w < 8; w++) t += wsum[w];
        g_task_loss[b] = t * (1.f / (float)NQRY);
        __threadfence();
        unsigned int v = atomicAdd(&g_ticket, 1u);
        *flag = ((v + 1u) % NTASK == 0u) ? 1 : 0;
    }
    __syncthreads();

    // last-arriving CTA performs the deterministic final reduction
    if (*flag) {
        __threadfence();
        float x = __ldcg(&g_task_loss[tid]);
        float* red = proto;   // reuse smem
        red[tid] = x;
        __syncthreads();
        #pragma unroll
        for (int off = 128; off; off >>= 1) {
            if (tid < off) red[tid] += red[tid + off];
            __syncthreads();
        }
        if (tid == 0) out[0] = red[0] * (1.f / (float)NTASK);
    }
}

extern "C" void kernel_launch(void* const* d_in, const int* in_sizes, int n_in,
                              void* d_out, int out_size) {
    const float* sup = (const float*)d_in[0];
    const float* qry = (const float*)d_in[1];
    const int*   ts  = (const int*)d_in[2];
    const int*   tq  = (const int*)d_in[3];
    float* out = (float*)d_out;

    const size_t SMEM = (size_t)(NCLS * DDIM + NCLS + 8) * sizeof(float)
                      + (size_t)(NCLS + NSUP + NQRY + 1) * sizeof(int);
    cudaFuncSetAttribute(proto_loss_kernel,
                         cudaFuncAttributeMaxDynamicSharedMemorySize, (int)SMEM);
    proto_loss_kernel<<<NTASK, THREADS, SMEM>>>(sup, qry, ts, tq, out);
}